// round 6
// baseline (speedup 1.0000x reference)
#include <cuda_runtime.h>
#include <cuda_fp16.h>
#include <math.h>

#define NMAX   50000
#define EMAX   400000
#define D      64
#define DD     128
#define NBND   64
#define NROWS  65

// Device scratch (zero-initialized at module load; each full launch sequence
// leaves them zeroed again, so graph replays are deterministic)
__device__ __align__(16) float   g_acc[NMAX * DD];
__device__ float  g_accs[NMAX];
__device__ int    g_din[NMAX];
__device__ int    g_dout[NMAX];
__device__ __align__(16) __half2 g_feath[NMAX * 32];
__device__ __align__(16) __half  g_t2h[NROWS * D];

__device__ __forceinline__ void red_add_v4(float* p, float4 v) {
    asm volatile("red.global.add.v4.f32 [%0], {%1, %2, %3, %4};"
                 :: "l"(p), "f"(v.x), "f"(v.y), "f"(v.z), "f"(v.w)
                 : "memory");
}

__device__ __forceinline__ void fmaf2(unsigned long long& c,
                                      unsigned long long a,
                                      unsigned long long b) {
    asm("fma.rn.f32x2 %0, %1, %2, %0;" : "+l"(c) : "l"(a), "l"(b));
}

__device__ __forceinline__ void acc_prod(uint4 tv, uint4 fv, float4& ca, float4& cb) {
    const __half2* th = (const __half2*)&tv;
    const __half2* fh = (const __half2*)&fv;
    float2 t0 = __half22float2(th[0]), f0 = __half22float2(fh[0]);
    float2 t1 = __half22float2(th[1]), f1 = __half22float2(fh[1]);
    float2 t2 = __half22float2(th[2]), f2 = __half22float2(fh[2]);
    float2 t3 = __half22float2(th[3]), f3 = __half22float2(fh[3]);
    ca.x = fmaf(t0.x, f0.x, ca.x); ca.y = fmaf(t0.y, f0.y, ca.y);
    ca.z = fmaf(t1.x, f1.x, ca.z); ca.w = fmaf(t1.y, f1.y, ca.w);
    cb.x = fmaf(t2.x, f2.x, cb.x); cb.y = fmaf(t2.y, f2.y, cb.y);
    cb.z = fmaf(t3.x, f3.x, cb.z); cb.w = fmaf(t3.y, f3.y, cb.w);
}

// ---------------------------------------------------------------------------
// 0) setup: convert feat -> fp16, fused table, degree counts (counters were
//    zeroed by the previous gemm pass / initial load)
__global__ void setup_kernel(const float* __restrict__ feat,
                             const float* __restrict__ embed,
                             const float* __restrict__ Gw,
                             const int* __restrict__ src,
                             const int* __restrict__ dst,
                             int n, int e) {
    int i = blockIdx.x * blockDim.x + threadIdx.x;
    int stride = gridDim.x * blockDim.x;

    int toth = n * 32;
    for (int k = i; k < toth; k += stride) {
        float2 v = ((const float2*)feat)[k];
        g_feath[k] = __floats2half2_rn(v.x, v.y);
    }
    for (int k = i; k < e; k += stride) {
        atomicAdd(&g_din[dst[k]], 1);
        atomicAdd(&g_dout[src[k]], 1);
    }
    for (int t = i; t < NROWS * D; t += stride) {
        int r = t >> 6;
        int d = t & 63;
        float s = 0.f;
#pragma unroll
        for (int k = 0; k < 32; k++)
            s = fmaf(embed[r * 32 + k], Gw[d * 32 + k], s);
        g_t2h[t] = __float2half_rn(s);
    }
}

// ---------------------------------------------------------------------------
// 1) edge kernel: 8 lanes/edge, O(1) bucket guess+fixup, batched gathers.
__global__ void __launch_bounds__(256) edge_kernel(
        const float2* __restrict__ loc,
        const float* __restrict__ bnd,
        const int* __restrict__ src,
        const int* __restrict__ dst,
        const int* __restrict__ inter,
        int e) {
    __shared__ float sb[NBND];
    if (threadIdx.x < NBND) sb[threadIdx.x] = bnd[threadIdx.x];
    __syncthreads();
    // scale for the arithmetic index guess: boundaries ~ linspace(0, bmax, 64)
    float guess_scale = 63.0f / fmaxf(sb[NBND - 1], 1e-20f);

    int gtid  = blockIdx.x * blockDim.x + threadIdx.x;
    int eidx0 = gtid >> 3;
    int sub   = threadIdx.x & 7;
    int lane  = threadIdx.x & 31;
    int base  = lane & 24;

    bool valid = (eidx0 < e);
    int eidx = valid ? eidx0 : 0;

    int s = src[eidx];
    int d = dst[eidx];
    int din  = g_din[d];    // issue early
    int dout = g_dout[s];
    float2 ls = loc[s];

    int id = 0;
    if (sub >= 1 && sub <= 5) id = inter[eidx * 5 + (sub - 1)];

    int bk = 0;
    if (sub < 6) {
        float2 o = (sub == 0) ? loc[d] : loc[id];
        float dx = o.x - ls.x;
        float dy = o.y - ls.y;
        float v = sqrtf(dx * dx + dy * dy);
        // searchsorted(side=left): first k with sb[k] >= v.
        // Arithmetic guess assuming uniform grid, then exact fixup (correct
        // for any sorted boundaries; O(1) steps for near-uniform ones).
        int k = (int)ceilf(v * guess_scale);
        k = min(NBND, max(0, k));
        while (k > 0 && sb[k - 1] >= v) --k;
        while (k < NBND && sb[k] < v) ++k;
        bk = k;
    }

    const unsigned FULL = 0xffffffffu;
    const uint4* t4 = (const uint4*)g_t2h;
    const uint4* f4 = (const uint4*)g_feath;

    // broadcast all buckets/ids, then batch all 12 gathers (max MLP)
    int bks[6], ids[6];
#pragma unroll
    for (int j = 0; j < 6; j++) bks[j] = __shfl_sync(FULL, bk, base + j);
    ids[0] = s;
#pragma unroll
    for (int j = 1; j < 6; j++) ids[j] = __shfl_sync(FULL, id, base + j);

    uint4 tv[6], fv[6];
#pragma unroll
    for (int j = 0; j < 6; j++) tv[j] = t4[bks[j] * 8 + sub];
#pragma unroll
    for (int j = 0; j < 6; j++) fv[j] = f4[ids[j] * 8 + sub];

    float4 c0a = make_float4(0.f, 0.f, 0.f, 0.f);
    float4 c0b = make_float4(0.f, 0.f, 0.f, 0.f);
    acc_prod(tv[0], fv[0], c0a, c0b);

    float4 c1a = make_float4(0.f, 0.f, 0.f, 0.f);
    float4 c1b = make_float4(0.f, 0.f, 0.f, 0.f);
#pragma unroll
    for (int j = 1; j < 6; j++) acc_prod(tv[j], fv[j], c1a, c1b);

    float sc = rsqrtf(fmaxf((float)din, 1.f)) *
               rsqrtf(fmaxf((float)dout, 1.f));
    float m = 0.2f * sc;
    c0a.x *= sc; c0a.y *= sc; c0a.z *= sc; c0a.w *= sc;
    c0b.x *= sc; c0b.y *= sc; c0b.z *= sc; c0b.w *= sc;
    c1a.x *= m;  c1a.y *= m;  c1a.z *= m;  c1a.w *= m;
    c1b.x *= m;  c1b.y *= m;  c1b.z *= m;  c1b.w *= m;

    if (valid) {
        float* p0 = g_acc + d * DD + sub * 8;
        red_add_v4(p0,         c0a);
        red_add_v4(p0 + 4,     c0b);
        red_add_v4(p0 + D,     c1a);
        red_add_v4(p0 + D + 4, c1b);
        if (sub == 0) atomicAdd(&g_accs[d], sc);
    }
}

// ---------------------------------------------------------------------------
// 2) persistent GEMM + scratch re-zeroing (for the next graph replay)
#define KP 130
__global__ void gemm_kernel(const float* __restrict__ aggw,
                            const float* __restrict__ aggb,
                            float* __restrict__ out, int n) {
    __shared__ float Ws[D * KP];
    __shared__ float As[16 * KP];
    __shared__ float Ss[16];
    __shared__ float Bs[D];

    int tid = threadIdx.x;
    int gi = blockIdx.x * blockDim.x + tid;
    int gstride = gridDim.x * blockDim.x;

    // re-zero degree counters (consumed by edge_kernel already)
    for (int k = gi; k < n; k += gstride) {
        g_din[k]  = 0;
        g_dout[k] = 0;
    }

    for (int idx = tid; idx < D * DD; idx += 256) {
        int dd = idx >> 7;
        int k  = idx & 127;
        Ws[dd * KP + k] = aggw[idx];
    }
    if (tid < D) Bs[tid] = aggb[tid];

    int ntiles = (n + 15) >> 4;
    int w = tid >> 5;
    int l = tid & 31;
    const float4 z4 = make_float4(0.f, 0.f, 0.f, 0.f);

    for (int t = blockIdx.x; t < ntiles; t += gridDim.x) {
        int basev = t << 4;
        __syncthreads();
        for (int idx = tid; idx < 16 * 32; idx += 256) {
            int j = idx >> 5;
            int c = idx & 31;
            int node = basev + j;
            float4 v = z4;
            if (node < n) {
                v = ((const float4*)g_acc)[node * 32 + c];
                ((float4*)g_acc)[node * 32 + c] = z4;   // re-zero for next call
            }
            float* p = As + j * KP + c * 4;
            *(float2*)p       = make_float2(v.x, v.y);
            *(float2*)(p + 2) = make_float2(v.z, v.w);
        }
        if (tid < 16) {
            int node = basev + tid;
            float ss = 0.f;
            if (node < n) { ss = g_accs[node]; g_accs[node] = 0.f; }
            Ss[tid] = ss;
        }
        __syncthreads();

        const float* ar0 = As + (2 * w) * KP;
        const float* ar1 = As + (2 * w + 1) * KP;
        const float* wr0 = Ws + l * KP;
        const float* wr1 = Ws + (l + 32) * KP;

        unsigned long long acc00 = 0ull, acc01 = 0ull, acc10 = 0ull, acc11 = 0ull;
#pragma unroll 8
        for (int k = 0; k < DD; k += 2) {
            unsigned long long a0 = *(const unsigned long long*)(ar0 + k);
            unsigned long long a1 = *(const unsigned long long*)(ar1 + k);
            unsigned long long w0 = *(const unsigned long long*)(wr0 + k);
            unsigned long long w1 = *(const unsigned long long*)(wr1 + k);
            fmaf2(acc00, a0, w0);
            fmaf2(acc01, a0, w1);
            fmaf2(acc10, a1, w0);
            fmaf2(acc11, a1, w1);
        }

        float2 p00 = *(float2*)&acc00;
        float2 p01 = *(float2*)&acc01;
        float2 p10 = *(float2*)&acc10;
        float2 p11 = *(float2*)&acc11;

        int n0 = basev + 2 * w;
        int n1 = n0 + 1;
        if (n0 < n) {
            float ss = Ss[2 * w];
            out[n0 * D + l]      = (p00.x + p00.y) + ss * Bs[l];
            out[n0 * D + l + 32] = (p01.x + p01.y) + ss * Bs[l + 32];
        }
        if (n1 < n) {
            float ss = Ss[2 * w + 1];
            out[n1 * D + l]      = (p10.x + p10.y) + ss * Bs[l];
            out[n1 * D + l + 32] = (p11.x + p11.y) + ss * Bs[l + 32];
        }
    }
}

// ---------------------------------------------------------------------------
extern "C" void kernel_launch(void* const* d_in, const int* in_sizes, int n_in,
                              void* d_out, int out_size) {
    const float*  feat  = (const float*)d_in[0];
    const float2* loc   = (const float2*)d_in[1];
    const float*  embed = (const float*)d_in[2];
    const float*  Gw    = (const float*)d_in[3];
    const float*  aggw  = (const float*)d_in[4];
    const float*  aggb  = (const float*)d_in[5];
    const float*  bnd   = (const float*)d_in[6];
    const int*    src   = (const int*)d_in[7];
    const int*    dst   = (const int*)d_in[8];
    const int*    inter = (const int*)d_in[9];
    float* out = (float*)d_out;

    int n = in_sizes[0] / D;   // 50000
    int e = in_sizes[7];       // 400000

    setup_kernel<<<4096, 256>>>(feat, embed, Gw, src, dst, n, e);

    long long threads_needed = (long long)e * 8;
    int blocks = (int)((threads_needed + 255) / 256);
    edge_kernel<<<blocks, 256>>>(loc, bnd, src, dst, inter, e);

    gemm_kernel<<<740, 256>>>(aggw, aggb, out, n);
}

// round 7
// speedup vs baseline: 1.0906x; 1.0906x over previous
#include <cuda_runtime.h>
#include <cuda_fp16.h>
#include <math.h>

#define NMAX   50000
#define EMAX   400000
#define D      64
#define DD     128
#define NBND   64
#define NROWS  65

// Device scratch (zero-init at load; replay-deterministic: setup re-zeroes
// g_acc/g_accs each call, gemm re-zeroes din/dout each call)
__device__ __align__(16) float   g_acc[NMAX * DD];
__device__ float  g_accs[NMAX];
__device__ int    g_din[NMAX];
__device__ int    g_dout[NMAX];
__device__ __align__(16) __half2 g_feath[NMAX * 32];
__device__ __align__(16) __half  g_t2h[NROWS * D];

__device__ __forceinline__ void red_add_v4(float* p, float4 v) {
    asm volatile("red.global.add.v4.f32 [%0], {%1, %2, %3, %4};"
                 :: "l"(p), "f"(v.x), "f"(v.y), "f"(v.z), "f"(v.w)
                 : "memory");
}

__device__ __forceinline__ void fmaf2(unsigned long long& c,
                                      unsigned long long a,
                                      unsigned long long b) {
    asm("fma.rn.f32x2 %0, %1, %2, %0;" : "+l"(c) : "l"(a), "l"(b));
}

__device__ __forceinline__ void acc_prod(uint4 tv, uint4 fv, float4& ca, float4& cb) {
    const __half2* th = (const __half2*)&tv;
    const __half2* fh = (const __half2*)&fv;
    float2 t0 = __half22float2(th[0]), f0 = __half22float2(fh[0]);
    float2 t1 = __half22float2(th[1]), f1 = __half22float2(fh[1]);
    float2 t2 = __half22float2(th[2]), f2 = __half22float2(fh[2]);
    float2 t3 = __half22float2(th[3]), f3 = __half22float2(fh[3]);
    ca.x = fmaf(t0.x, f0.x, ca.x); ca.y = fmaf(t0.y, f0.y, ca.y);
    ca.z = fmaf(t1.x, f1.x, ca.z); ca.w = fmaf(t1.y, f1.y, ca.w);
    cb.x = fmaf(t2.x, f2.x, cb.x); cb.y = fmaf(t2.y, f2.y, cb.y);
    cb.z = fmaf(t3.x, f3.x, cb.z); cb.w = fmaf(t3.y, f3.y, cb.w);
}

// ---------------------------------------------------------------------------
// 0) setup: zero accumulators, convert feat->fp16, degrees, fused table.
__global__ void setup_kernel(const float* __restrict__ feat,
                             const float* __restrict__ embed,
                             const float* __restrict__ Gw,
                             const int* __restrict__ src,
                             const int* __restrict__ dst,
                             int n, int e) {
    int i = blockIdx.x * blockDim.x + threadIdx.x;
    int stride = gridDim.x * blockDim.x;

    int tot4 = n * (DD / 4);
    float4 z = make_float4(0.f, 0.f, 0.f, 0.f);
    for (int k = i; k < tot4; k += stride) ((float4*)g_acc)[k] = z;
    for (int k = i; k < n; k += stride) g_accs[k] = 0.f;

    int toth = n * 32;
    for (int k = i; k < toth; k += stride) {
        float2 v = ((const float2*)feat)[k];
        g_feath[k] = __floats2half2_rn(v.x, v.y);
    }
    for (int k = i; k < e; k += stride) {
        atomicAdd(&g_din[dst[k]], 1);
        atomicAdd(&g_dout[src[k]], 1);
    }
    for (int t = i; t < NROWS * D; t += stride) {
        int r = t >> 6;
        int d = t & 63;
        float s = 0.f;
#pragma unroll
        for (int k = 0; k < 32; k++)
            s = fmaf(embed[r * 32 + k], Gw[d * 32 + k], s);
        g_t2h[t] = __float2half_rn(s);
    }
}

// ---------------------------------------------------------------------------
// 1) edge kernel: 8 lanes/edge. Fused table in SMEM, O(1) bucket search,
//    feat rows prefetched (batched LDG.128), table read inline from smem.
__global__ void __launch_bounds__(256) edge_kernel(
        const float2* __restrict__ loc,
        const float* __restrict__ bnd,
        const int* __restrict__ src,
        const int* __restrict__ dst,
        const int* __restrict__ inter,
        int e) {
    __shared__ float sb[NBND];
    __shared__ uint4 ts[NROWS * 8];   // fp16 table rows: 8 uint4 per row

    if (threadIdx.x < NBND) sb[threadIdx.x] = bnd[threadIdx.x];
    {
        const uint4* tg = (const uint4*)g_t2h;
        for (int k = threadIdx.x; k < NROWS * 8; k += 256) ts[k] = tg[k];
    }
    __syncthreads();
    float guess_scale = 63.0f / fmaxf(sb[NBND - 1], 1e-20f);

    int gtid  = blockIdx.x * blockDim.x + threadIdx.x;
    int eidx0 = gtid >> 3;
    int sub   = threadIdx.x & 7;
    int lane  = threadIdx.x & 31;
    int base  = lane & 24;

    bool valid = (eidx0 < e);
    int eidx = valid ? eidx0 : 0;

    int s = src[eidx];
    int d = dst[eidx];
    int din  = g_din[d];
    int dout = g_dout[s];
    float2 ls = loc[s];

    int id = 0;
    if (sub >= 1 && sub <= 5) id = inter[eidx * 5 + (sub - 1)];

    int bk = 0;
    if (sub < 6) {
        float2 o = (sub == 0) ? loc[d] : loc[id];
        float dx = o.x - ls.x;
        float dy = o.y - ls.y;
        float v = sqrtf(dx * dx + dy * dy);
        // searchsorted(side=left): first k with sb[k] >= v. Arithmetic guess,
        // exact fixup (correct for any sorted boundaries).
        int k = (int)ceilf(v * guess_scale);
        k = min(NBND, max(0, k));
        while (k > 0 && sb[k - 1] >= v) --k;
        while (k < NBND && sb[k] < v) ++k;
        bk = k;
    }

    const unsigned FULL = 0xffffffffu;
    const uint4* f4 = (const uint4*)g_feath;

    // broadcast buckets/ids
    int bks[6], ids[6];
#pragma unroll
    for (int j = 0; j < 6; j++) bks[j] = __shfl_sync(FULL, bk, base + j);
    ids[0] = s;
#pragma unroll
    for (int j = 1; j < 6; j++) ids[j] = __shfl_sync(FULL, id, base + j);

    // batch the 6 long-latency random feat gathers
    uint4 fv[6];
#pragma unroll
    for (int j = 0; j < 6; j++) fv[j] = f4[ids[j] * 8 + sub];

    // table rows from smem, inline
    float4 c0a = make_float4(0.f, 0.f, 0.f, 0.f);
    float4 c0b = make_float4(0.f, 0.f, 0.f, 0.f);
    acc_prod(ts[bks[0] * 8 + sub], fv[0], c0a, c0b);

    float4 c1a = make_float4(0.f, 0.f, 0.f, 0.f);
    float4 c1b = make_float4(0.f, 0.f, 0.f, 0.f);
#pragma unroll
    for (int j = 1; j < 6; j++)
        acc_prod(ts[bks[j] * 8 + sub], fv[j], c1a, c1b);

    float sc = rsqrtf(fmaxf((float)din, 1.f)) *
               rsqrtf(fmaxf((float)dout, 1.f));
    float m = 0.2f * sc;
    c0a.x *= sc; c0a.y *= sc; c0a.z *= sc; c0a.w *= sc;
    c0b.x *= sc; c0b.y *= sc; c0b.z *= sc; c0b.w *= sc;
    c1a.x *= m;  c1a.y *= m;  c1a.z *= m;  c1a.w *= m;
    c1b.x *= m;  c1b.y *= m;  c1b.z *= m;  c1b.w *= m;

    if (valid) {
        float* p0 = g_acc + d * DD + sub * 8;
        red_add_v4(p0,         c0a);
        red_add_v4(p0 + 4,     c0b);
        red_add_v4(p0 + D,     c1a);
        red_add_v4(p0 + D + 4, c1b);
        if (sub == 0) atomicAdd(&g_accs[d], sc);
    }
}

// ---------------------------------------------------------------------------
// 2) persistent GEMM (read-only on g_acc) + re-zero degree counters.
#define KP 130
__global__ void gemm_kernel(const float* __restrict__ aggw,
                            const float* __restrict__ aggb,
                            float* __restrict__ out, int n) {
    __shared__ float Ws[D * KP];
    __shared__ float As[16 * KP];
    __shared__ float Ss[16];
    __shared__ float Bs[D];

    int tid = threadIdx.x;
    int gi = blockIdx.x * blockDim.x + tid;
    int gstride = gridDim.x * blockDim.x;

    // re-zero degree counters for the next replay (consumed already)
    for (int k = gi; k < n; k += gstride) {
        g_din[k]  = 0;
        g_dout[k] = 0;
    }

    for (int idx = tid; idx < D * DD; idx += 256) {
        int dd = idx >> 7;
        int k  = idx & 127;
        Ws[dd * KP + k] = aggw[idx];
    }
    if (tid < D) Bs[tid] = aggb[tid];

    int ntiles = (n + 15) >> 4;
    int w = tid >> 5;
    int l = tid & 31;

    for (int t = blockIdx.x; t < ntiles; t += gridDim.x) {
        int basev = t << 4;
        __syncthreads();
        for (int idx = tid; idx < 16 * 32; idx += 256) {
            int j = idx >> 5;
            int c = idx & 31;
            int node = basev + j;
            float4 v = make_float4(0.f, 0.f, 0.f, 0.f);
            if (node < n) v = ((const float4*)g_acc)[node * 32 + c];
            float* p = As + j * KP + c * 4;
            *(float2*)p       = make_float2(v.x, v.y);
            *(float2*)(p + 2) = make_float2(v.z, v.w);
        }
        if (tid < 16) Ss[tid] = (basev + tid < n) ? g_accs[basev + tid] : 0.f;
        __syncthreads();

        const float* ar0 = As + (2 * w) * KP;
        const float* ar1 = As + (2 * w + 1) * KP;
        const float* wr0 = Ws + l * KP;
        const float* wr1 = Ws + (l + 32) * KP;

        unsigned long long acc00 = 0ull, acc01 = 0ull, acc10 = 0ull, acc11 = 0ull;
#pragma unroll 8
        for (int k = 0; k < DD; k += 2) {
            unsigned long long a0 = *(const unsigned long long*)(ar0 + k);
            unsigned long long a1 = *(const unsigned long long*)(ar1 + k);
            unsigned long long w0 = *(const unsigned long long*)(wr0 + k);
            unsigned long long w1 = *(const unsigned long long*)(wr1 + k);
            fmaf2(acc00, a0, w0);
            fmaf2(acc01, a0, w1);
            fmaf2(acc10, a1, w0);
            fmaf2(acc11, a1, w1);
        }

        float2 p00 = *(float2*)&acc00;
        float2 p01 = *(float2*)&acc01;
        float2 p10 = *(float2*)&acc10;
        float2 p11 = *(float2*)&acc11;

        int n0 = basev + 2 * w;
        int n1 = n0 + 1;
        if (n0 < n) {
            float ss = Ss[2 * w];
            out[n0 * D + l]      = (p00.x + p00.y) + ss * Bs[l];
            out[n0 * D + l + 32] = (p01.x + p01.y) + ss * Bs[l + 32];
        }
        if (n1 < n) {
            float ss = Ss[2 * w + 1];
            out[n1 * D + l]      = (p10.x + p10.y) + ss * Bs[l];
            out[n1 * D + l + 32] = (p11.x + p11.y) + ss * Bs[l + 32];
        }
    }
}

// ---------------------------------------------------------------------------
extern "C" void kernel_launch(void* const* d_in, const int* in_sizes, int n_in,
                              void* d_out, int out_size) {
    const float*  feat  = (const float*)d_in[0];
    const float2* loc   = (const float2*)d_in[1];
    const float*  embed = (const float*)d_in[2];
    const float*  Gw    = (const float*)d_in[3];
    const float*  aggw  = (const float*)d_in[4];
    const float*  aggb  = (const float*)d_in[5];
    const float*  bnd   = (const float*)d_in[6];
    const int*    src   = (const int*)d_in[7];
    const int*    dst   = (const int*)d_in[8];
    const int*    inter = (const int*)d_in[9];
    float* out = (float*)d_out;

    int n = in_sizes[0] / D;   // 50000
    int e = in_sizes[7];       // 400000

    setup_kernel<<<4096, 256>>>(feat, embed, Gw, src, dst, n, e);

    long long threads_needed = (long long)e * 8;
    int blocks = (int)((threads_needed + 255) / 256);
    edge_kernel<<<blocks, 256>>>(loc, bnd, src, dst, inter, e);

    gemm_kernel<<<740, 256>>>(aggw, aggb, out, n);
}